// round 1
// baseline (speedup 1.0000x reference)
#include <cuda_runtime.h>
#include <math_constants.h>

#define BB 32
#define CC 9
#define TT 4096
#define NC 512
#define CD 64

// scratch for per-channel phases (B,C,T)
__device__ float g_phase[BB * CC * TT];

__device__ __forceinline__ float2 cmulf(float2 a, float2 b) {
    return make_float2(a.x * b.x - a.y * b.y, a.x * b.y + a.y * b.x);
}

// One block per (b,c) row: fwd DIF FFT -> Hilbert multiplier (bit-reversed
// domain) -> inv DIT FFT -> atan2 phase. 4096-pt radix-2, all in shared.
__global__ void fft_phase_kernel(const float* __restrict__ imu) {
    __shared__ float2 s[TT];  // 32 KB
    const int row = blockIdx.x;  // b*C + c
    const float* x = imu + (size_t)row * TT;
    const int tid = threadIdx.x;

    for (int t = tid; t < TT; t += blockDim.x)
        s[t] = make_float2(x[t], 0.0f);
    __syncthreads();

    // Forward DIF (Gentleman-Sande): natural in, bit-reversed out.
    for (int lg = 11; lg >= 0; --lg) {
        const int len = 1 << lg;
        for (int i = tid; i < TT / 2; i += blockDim.x) {
            const int j = i & (len - 1);
            const int base = (i >> lg) << (lg + 1);
            const int i0 = base + j, i1 = i0 + len;
            float2 u = s[i0], v = s[i1];
            float sn, cs;
            sincosf(-(float)CUDART_PI_F * (float)j / (float)len, &sn, &cs);
            s[i0] = make_float2(u.x + v.x, u.y + v.y);
            float2 d = make_float2(u.x - v.x, u.y - v.y);
            s[i1] = cmulf(d, make_float2(cs, sn));
        }
        __syncthreads();
    }

    // Hilbert multiplier h[k] applied at bit-reversed slot.
    for (int p = tid; p < TT; p += blockDim.x) {
        const int k = (int)(__brev((unsigned)p) >> 20);  // 12-bit reverse
        float h;
        if (k == 0 || k == TT / 2) h = 1.0f;
        else if (k < TT / 2)       h = 2.0f;
        else                       h = 0.0f;
        s[p].x *= h;
        s[p].y *= h;
    }
    __syncthreads();

    // Inverse DIT (Cooley-Tukey): bit-reversed in, natural out.
    // Skip the 1/N scale: angle() is scale-invariant.
    for (int lg = 0; lg <= 11; ++lg) {
        const int len = 1 << lg;
        for (int i = tid; i < TT / 2; i += blockDim.x) {
            const int j = i & (len - 1);
            const int base = (i >> lg) << (lg + 1);
            const int i0 = base + j, i1 = i0 + len;
            float sn, cs;
            sincosf((float)CUDART_PI_F * (float)j / (float)len, &sn, &cs);
            float2 u = s[i0];
            float2 v = cmulf(s[i1], make_float2(cs, sn));
            s[i0] = make_float2(u.x + v.x, u.y + v.y);
            s[i1] = make_float2(u.x - v.x, u.y - v.y);
        }
        __syncthreads();
    }

    float* ph = g_phase + (size_t)row * TT;
    for (int t = tid; t < TT; t += blockDim.x)
        ph[t] = atan2f(s[t].y, s[t].x);
}

// One thread per (b,t): phase mean over channels, two small linears,
// 512-code argmin over 64 dims (codebook + norms in shared), outputs.
__global__ void quant_kernel(const float* __restrict__ imu,
                             const float* __restrict__ Wm,
                             const float* __restrict__ bm,
                             const float* __restrict__ Wp,
                             const float* __restrict__ bp,
                             const float* __restrict__ cb,
                             float* __restrict__ out) {
    extern __shared__ float sm[];
    float* scb = sm;              // 512*64 codebook
    float* cn = sm + NC * CD;     // 512 squared norms
    const int tid = threadIdx.x;

    for (int i = tid; i < NC * CD / 4; i += blockDim.x)
        ((float4*)scb)[i] = ((const float4*)cb)[i];
    __syncthreads();
    for (int k = tid; k < NC; k += blockDim.x) {
        float a = 0.0f;
#pragma unroll
        for (int d = 0; d < CD; ++d) {
            float v = scb[k * CD + d];
            a += v * v;
        }
        cn[k] = a;
    }
    __syncthreads();

    const int p = blockIdx.x * blockDim.x + tid;  // [0, B*T)
    const int b = p >> 12;
    const int t = p & (TT - 1);

    const float* xb = imu + (size_t)b * CC * TT + t;
    float xc[9];
#pragma unroll
    for (int c = 0; c < 9; ++c) xc[c] = xb[c * TT];

    const float* phb = g_phase + (size_t)b * CC * TT + t;
    float pm = 0.0f;
#pragma unroll
    for (int c = 0; c < 9; ++c) pm += phb[c * TT];
    pm *= (1.0f / 9.0f);
    float sp, cp;
    sincosf(pm, &sp, &cp);

    float f[64];
#pragma unroll
    for (int i = 0; i < 32; ++i) {
        float a = bm[i];
#pragma unroll
        for (int c = 0; c < 9; ++c) a += Wm[i * 9 + c] * xc[c];
        f[i] = a;
    }
    float comb[9];
#pragma unroll
    for (int c = 0; c < 7; ++c) comb[c] = xc[c];
    comb[7] = cp;
    comb[8] = sp;
#pragma unroll
    for (int i = 0; i < 32; ++i) {
        float a = bp[i];
#pragma unroll
        for (int c = 0; c < 9; ++c) a += Wp[i * 9 + c] * comb[c];
        f[32 + i] = a;
    }

    // argmin_k ||f - c_k||^2 == argmin_k (||c_k||^2 - 2 f.c_k)
    float best = CUDART_INF_F;
    int bk = 0;
    const float4* cb4 = (const float4*)scb;
#pragma unroll 1
    for (int k = 0; k < NC; k += 2) {
        float a0 = 0.0f, a1 = 0.0f;
#pragma unroll
        for (int q = 0; q < 16; ++q) {
            float4 c0 = cb4[k * 16 + q];
            float4 c1 = cb4[k * 16 + 16 + q];
            a0 += f[4 * q + 0] * c0.x + f[4 * q + 1] * c0.y +
                  f[4 * q + 2] * c0.z + f[4 * q + 3] * c0.w;
            a1 += f[4 * q + 0] * c1.x + f[4 * q + 1] * c1.y +
                  f[4 * q + 2] * c1.z + f[4 * q + 3] * c1.w;
        }
        const float s0 = cn[k] - 2.0f * a0;
        const float s1 = cn[k + 1] - 2.0f * a1;
        if (s0 < best) { best = s0; bk = k; }
        if (s1 < best) { best = s1; bk = k + 1; }
    }

    // outputs: quantized (B*T*64) || indices-as-float (B*T) || phases (B*T)
    float4* qd = (float4*)(out + (size_t)p * CD);
    const float4* src = cb4 + bk * 16;
#pragma unroll
    for (int i = 0; i < 16; ++i) qd[i] = src[i];
    out[(size_t)BB * TT * CD + p] = (float)bk;
    out[(size_t)BB * TT * CD + (size_t)BB * TT + p] = pm;
}

extern "C" void kernel_launch(void* const* d_in, const int* in_sizes, int n_in,
                              void* d_out, int out_size) {
    const float* imu = (const float*)d_in[0];
    const float* Wm  = (const float*)d_in[1];
    const float* bm  = (const float*)d_in[2];
    const float* Wp  = (const float*)d_in[3];
    const float* bp  = (const float*)d_in[4];
    const float* cb  = (const float*)d_in[5];
    float* out = (float*)d_out;

    fft_phase_kernel<<<BB * CC, 256>>>(imu);

    const int smem = (NC * CD + NC) * (int)sizeof(float);  // 133120 B
    cudaFuncSetAttribute(quant_kernel,
                         cudaFuncAttributeMaxDynamicSharedMemorySize, smem);
    quant_kernel<<<(BB * TT) / 256, 256, smem>>>(imu, Wm, bm, Wp, bp, cb, out);
}

// round 2
// speedup vs baseline: 1.4642x; 1.4642x over previous
#include <cuda_runtime.h>
#include <math_constants.h>

#define BB 32
#define CC 9
#define TT 4096
#define NC 512
#define CD 64
#define MBLK 128          // positions per block
#define NTHREADS 256

// scratch for per-channel phases (B,C,T)
__device__ float g_phase[BB * CC * TT];

__device__ __forceinline__ float2 cmulf(float2 a, float2 b) {
    return make_float2(a.x * b.x - a.y * b.y, a.x * b.y + a.y * b.x);
}

// One block per (b,c) row: fwd DIF FFT -> Hilbert multiplier (bit-reversed
// domain) -> inv DIT FFT -> atan2 phase. 4096-pt radix-2, all in shared.
__global__ void fft_phase_kernel(const float* __restrict__ imu) {
    __shared__ float2 s[TT];  // 32 KB
    const int row = blockIdx.x;  // b*C + c
    const float* x = imu + (size_t)row * TT;
    const int tid = threadIdx.x;

    for (int t = tid; t < TT; t += blockDim.x)
        s[t] = make_float2(x[t], 0.0f);
    __syncthreads();

    // Forward DIF (Gentleman-Sande): natural in, bit-reversed out.
    for (int lg = 11; lg >= 0; --lg) {
        const int len = 1 << lg;
        for (int i = tid; i < TT / 2; i += blockDim.x) {
            const int j = i & (len - 1);
            const int base = (i >> lg) << (lg + 1);
            const int i0 = base + j, i1 = i0 + len;
            float2 u = s[i0], v = s[i1];
            float sn, cs;
            sincosf(-(float)CUDART_PI_F * (float)j / (float)len, &sn, &cs);
            s[i0] = make_float2(u.x + v.x, u.y + v.y);
            float2 d = make_float2(u.x - v.x, u.y - v.y);
            s[i1] = cmulf(d, make_float2(cs, sn));
        }
        __syncthreads();
    }

    // Hilbert multiplier h[k] applied at bit-reversed slot.
    for (int p = tid; p < TT; p += blockDim.x) {
        const int k = (int)(__brev((unsigned)p) >> 20);  // 12-bit reverse
        float h;
        if (k == 0 || k == TT / 2) h = 1.0f;
        else if (k < TT / 2)       h = 2.0f;
        else                       h = 0.0f;
        s[p].x *= h;
        s[p].y *= h;
    }
    __syncthreads();

    // Inverse DIT (Cooley-Tukey): bit-reversed in, natural out.
    // Skip 1/N: angle() is scale-invariant.
    for (int lg = 0; lg <= 11; ++lg) {
        const int len = 1 << lg;
        for (int i = tid; i < TT / 2; i += blockDim.x) {
            const int j = i & (len - 1);
            const int base = (i >> lg) << (lg + 1);
            const int i0 = base + j, i1 = i0 + len;
            float sn, cs;
            sincosf((float)CUDART_PI_F * (float)j / (float)len, &sn, &cs);
            float2 u = s[i0];
            float2 v = cmulf(s[i1], make_float2(cs, sn));
            s[i0] = make_float2(u.x + v.x, u.y + v.y);
            s[i1] = make_float2(u.x - v.x, u.y - v.y);
        }
        __syncthreads();
    }

    float* ph = g_phase + (size_t)row * TT;
    for (int t = tid; t < TT; t += blockDim.x)
        ph[t] = atan2f(s[t].y, s[t].x);
}

// Register-tiled distance-GEMM + argmin.
// Block: 128 positions x 512 codes, 256 threads as 16(pos-groups) x 16(code-lanes).
// Each thread: 8 pos x 8 codes accumulator tile, 4 chunks of 128 codes.
__global__ void __launch_bounds__(NTHREADS, 1)
quant_kernel(const float* __restrict__ imu,
             const float* __restrict__ Wm,
             const float* __restrict__ bm,
             const float* __restrict__ Wp,
             const float* __restrict__ bp,
             const float* __restrict__ cb,
             float* __restrict__ out) {
    extern __shared__ float sm[];
    float* scb_t = sm;                       // [64][512] transposed codebook
    float* f_t   = sm + NC * CD;             // [64][128] transposed features
    float* cn    = f_t + CD * MBLK;          // [512] squared norms
    int*   bk_s  = (int*)(cn + NC);          // [128] chosen indices

    const int tid = threadIdx.x;
    const int ty = tid >> 4;                 // 0..15 : position group (8 pos)
    const int tx = tid & 15;                 // 0..15 : code lane
    const int pbase = blockIdx.x * MBLK;     // first position of block

    // ---- Phase 1a: transposed codebook load (kq-major for conflict-free STS)
    const float4* cb4g = (const float4*)cb;
    for (int q = tid; q < NC * (CD / 4); q += NTHREADS) {
        const int kq = q >> 9;               // 0..15
        const int c  = q & (NC - 1);         // 0..511
        float4 v = cb4g[c * (CD / 4) + kq];
        scb_t[(4 * kq + 0) * NC + c] = v.x;
        scb_t[(4 * kq + 1) * NC + c] = v.y;
        scb_t[(4 * kq + 2) * NC + c] = v.z;
        scb_t[(4 * kq + 3) * NC + c] = v.w;
    }
    __syncthreads();

    // ---- Phase 1b: features (threads 0..127), code norms (all threads, 2 each)
    {
        const int c0 = tid * 2;
        float a0 = 0.0f, a1 = 0.0f;
#pragma unroll
        for (int k = 0; k < CD; ++k) {
            float v0 = scb_t[k * NC + c0];
            float v1 = scb_t[k * NC + c0 + 1];
            a0 += v0 * v0;
            a1 += v1 * v1;
        }
        cn[c0] = a0;
        cn[c0 + 1] = a1;
    }
    if (tid < MBLK) {
        const int p = pbase + tid;
        const int b = p >> 12;
        const int t = p & (TT - 1);

        const float* xb = imu + (size_t)b * CC * TT + t;
        float xc[9];
#pragma unroll
        for (int c = 0; c < 9; ++c) xc[c] = xb[c * TT];

        const float* phb = g_phase + (size_t)b * CC * TT + t;
        float pm = 0.0f;
#pragma unroll
        for (int c = 0; c < 9; ++c) pm += phb[c * TT];
        pm *= (1.0f / 9.0f);
        float sp, cp;
        sincosf(pm, &sp, &cp);
        out[(size_t)BB * TT * CD + (size_t)BB * TT + p] = pm;  // phases

#pragma unroll
        for (int i = 0; i < 32; ++i) {
            float a = bm[i];
#pragma unroll
            for (int c = 0; c < 9; ++c) a += Wm[i * 9 + c] * xc[c];
            f_t[i * MBLK + tid] = a;
        }
        float comb[9];
#pragma unroll
        for (int c = 0; c < 7; ++c) comb[c] = xc[c];
        comb[7] = cp;
        comb[8] = sp;
#pragma unroll
        for (int i = 0; i < 32; ++i) {
            float a = bp[i];
#pragma unroll
            for (int c = 0; c < 9; ++c) a += Wp[i * 9 + c] * comb[c];
            f_t[(32 + i) * MBLK + tid] = a;
        }
    }
    __syncthreads();

    // ---- Phase 2: distance GEMM + running argmin
    float best[8];
    int bidx[8];
#pragma unroll
    for (int i = 0; i < 8; ++i) { best[i] = CUDART_INF_F; bidx[i] = 0; }

    const int arow = ty * 8;
#pragma unroll 1
    for (int chunk = 0; chunk < 4; ++chunk) {
        const int cbase = chunk * 128 + tx * 4;   // codes cbase..+3, cbase+64..+67
        float acc[8][8];
#pragma unroll
        for (int i = 0; i < 8; ++i)
#pragma unroll
            for (int j = 0; j < 8; ++j) acc[i][j] = 0.0f;

#pragma unroll 2
        for (int k = 0; k < CD; ++k) {
            float4 a0 = *(const float4*)&f_t[k * MBLK + arow];
            float4 a1 = *(const float4*)&f_t[k * MBLK + arow + 4];
            float4 b0 = *(const float4*)&scb_t[k * NC + cbase];
            float4 b1 = *(const float4*)&scb_t[k * NC + cbase + 64];
            float av[8] = {a0.x, a0.y, a0.z, a0.w, a1.x, a1.y, a1.z, a1.w};
            float bv[8] = {b0.x, b0.y, b0.z, b0.w, b1.x, b1.y, b1.z, b1.w};
#pragma unroll
            for (int i = 0; i < 8; ++i)
#pragma unroll
                for (int j = 0; j < 8; ++j) acc[i][j] += av[i] * bv[j];
        }

#pragma unroll
        for (int j = 0; j < 8; ++j) {
            const int c = (j < 4) ? (cbase + j) : (cbase + 60 + j);
            const float cnv = cn[c];
#pragma unroll
            for (int i = 0; i < 8; ++i) {
                const float s = cnv - 2.0f * acc[i][j];
                if (s < best[i] || (s == best[i] && c < bidx[i])) {
                    best[i] = s; bidx[i] = c;
                }
            }
        }
    }

    // ---- Reduce over the 16 code-lanes (same warp half, width 16)
#pragma unroll
    for (int off = 8; off >= 1; off >>= 1) {
#pragma unroll
        for (int i = 0; i < 8; ++i) {
            float ob = __shfl_down_sync(0xffffffffu, best[i], off, 16);
            int   oi = __shfl_down_sync(0xffffffffu, bidx[i], off, 16);
            if (ob < best[i] || (ob == best[i] && oi < bidx[i])) {
                best[i] = ob; bidx[i] = oi;
            }
        }
    }
    if (tx == 0) {
#pragma unroll
        for (int i = 0; i < 8; ++i) {
            const int pos = arow + i;
            bk_s[pos] = bidx[i];
            out[(size_t)BB * TT * CD + (pbase + pos)] = (float)bidx[i];
        }
    }
    __syncthreads();

    // ---- Cooperative quantized-row copy from (L2-hot) global codebook
    for (int q = tid; q < MBLK * (CD / 4); q += NTHREADS) {
        const int pos = q >> 4;
        const int w = q & 15;
        ((float4*)(out + (size_t)(pbase + pos) * CD))[w] =
            cb4g[bk_s[pos] * (CD / 4) + w];
    }
}

extern "C" void kernel_launch(void* const* d_in, const int* in_sizes, int n_in,
                              void* d_out, int out_size) {
    const float* imu = (const float*)d_in[0];
    const float* Wm  = (const float*)d_in[1];
    const float* bm  = (const float*)d_in[2];
    const float* Wp  = (const float*)d_in[3];
    const float* bp  = (const float*)d_in[4];
    const float* cb  = (const float*)d_in[5];
    float* out = (float*)d_out;

    fft_phase_kernel<<<BB * CC, 256>>>(imu);

    const int smem = (NC * CD + CD * MBLK + NC) * (int)sizeof(float)
                     + MBLK * (int)sizeof(int);  // ~166.5 KB
    cudaFuncSetAttribute(quant_kernel,
                         cudaFuncAttributeMaxDynamicSharedMemorySize, smem);
    quant_kernel<<<(BB * TT) / MBLK, NTHREADS, smem>>>(imu, Wm, bm, Wp, bp, cb, out);
}

// round 4
// speedup vs baseline: 2.3158x; 1.5816x over previous
#include <cuda_runtime.h>
#include <cuda_bf16.h>
#include <math_constants.h>
#include <cstdint>

#define BB 32
#define CC 9
#define TT 4096
#define NC 512
#define CD 64
#define KTOT 192          // hi | lo | hi split-K
#define MBLK 128          // positions per block
#define KP_B 400          // padded SMEM row stride in bytes (200 bf16)

#define OFF_IDX ((size_t)BB * TT * CD)
#define OFF_PH  (OFF_IDX + (size_t)BB * TT)

// SMEM map (bytes)
#define SM_A   0u
#define SM_B   51200u
#define SM_CN  153600u
#define SM_IDX 155648u
#define SMEMSZ 156160

// ---------------- global scratch ----------------
__device__ float g_phase[BB * CC * TT];
__device__ __align__(16) __nv_bfloat16 g_B[NC * KTOT];   // 196 KB, segs (hi,hi,lo)
__device__ float g_cn[NC];

__device__ __forceinline__ uint32_t smem_to_u32(const void* p) {
    uint32_t a;
    asm("{ .reg .u64 t; cvta.to.shared.u64 t, %1; cvt.u32.u64 %0, t; }"
        : "=r"(a) : "l"(p));
    return a;
}

#define LDSM_X4(r0, r1, r2, r3, addr) \
    asm volatile("ldmatrix.sync.aligned.m8n8.x4.shared.b16 {%0,%1,%2,%3}, [%4];" \
                 : "=r"(r0), "=r"(r1), "=r"(r2), "=r"(r3) : "r"(addr))

#define MMA16816(d, a, b0, b1) \
    asm volatile("mma.sync.aligned.m16n8k16.row.col.f32.bf16.bf16.f32 " \
                 "{%0,%1,%2,%3}, {%4,%5,%6,%7}, {%8,%9}, {%0,%1,%2,%3};" \
                 : "+f"((d)[0]), "+f"((d)[1]), "+f"((d)[2]), "+f"((d)[3]) \
                 : "r"((a)[0]), "r"((a)[1]), "r"((a)[2]), "r"((a)[3]), \
                   "r"(b0), "r"(b1))

__device__ __forceinline__ float2 cmulf(float2 a, float2 b) {
    return make_float2(a.x * b.x - a.y * b.y, a.x * b.y + a.y * b.x);
}

// ---------------- kernel 0: codebook -> bf16 split + norms ----------------
__global__ void convert_cb_kernel(const float* __restrict__ cb) {
    const int c = blockIdx.x * blockDim.x + threadIdx.x;
    if (c >= NC) return;
    const float* src = cb + (size_t)c * CD;
    uint32_t* row32 = (uint32_t*)(g_B + (size_t)c * KTOT);
    float n = 0.0f;
#pragma unroll
    for (int q = 0; q < CD / 2; ++q) {
        float v0 = src[2 * q], v1 = src[2 * q + 1];
        n += v0 * v0 + v1 * v1;
        __nv_bfloat16 h0 = __float2bfloat16(v0), h1 = __float2bfloat16(v1);
        __nv_bfloat16 l0 = __float2bfloat16(v0 - __bfloat162float(h0));
        __nv_bfloat16 l1 = __float2bfloat16(v1 - __bfloat162float(h1));
        uint32_t hp = ((uint32_t)__bfloat16_as_ushort(h1) << 16) | __bfloat16_as_ushort(h0);
        uint32_t lp = ((uint32_t)__bfloat16_as_ushort(l1) << 16) | __bfloat16_as_ushort(l0);
        row32[q] = hp;            // seg0: c_hi
        row32[32 + q] = hp;       // seg1: c_hi
        row32[64 + q] = lp;       // seg2: c_lo
    }
    g_cn[c] = n;
}

// ---------------- kernel 1: FFT phase (validated) ----------------
__global__ void fft_phase_kernel(const float* __restrict__ imu) {
    __shared__ float2 s[TT];
    const int row = blockIdx.x;
    const float* x = imu + (size_t)row * TT;
    const int tid = threadIdx.x;

    for (int t = tid; t < TT; t += blockDim.x)
        s[t] = make_float2(x[t], 0.0f);
    __syncthreads();

    for (int lg = 11; lg >= 0; --lg) {
        const int len = 1 << lg;
        for (int i = tid; i < TT / 2; i += blockDim.x) {
            const int j = i & (len - 1);
            const int base = (i >> lg) << (lg + 1);
            const int i0 = base + j, i1 = i0 + len;
            float2 u = s[i0], v = s[i1];
            float sn, cs;
            sincosf(-(float)CUDART_PI_F * (float)j / (float)len, &sn, &cs);
            s[i0] = make_float2(u.x + v.x, u.y + v.y);
            float2 d = make_float2(u.x - v.x, u.y - v.y);
            s[i1] = cmulf(d, make_float2(cs, sn));
        }
        __syncthreads();
    }
    for (int p = tid; p < TT; p += blockDim.x) {
        const int k = (int)(__brev((unsigned)p) >> 20);
        float h;
        if (k == 0 || k == TT / 2) h = 1.0f;
        else if (k < TT / 2)       h = 2.0f;
        else                       h = 0.0f;
        s[p].x *= h;
        s[p].y *= h;
    }
    __syncthreads();
    for (int lg = 0; lg <= 11; ++lg) {
        const int len = 1 << lg;
        for (int i = tid; i < TT / 2; i += blockDim.x) {
            const int j = i & (len - 1);
            const int base = (i >> lg) << (lg + 1);
            const int i0 = base + j, i1 = i0 + len;
            float sn, cs;
            sincosf((float)CUDART_PI_F * (float)j / (float)len, &sn, &cs);
            float2 u = s[i0];
            float2 v = cmulf(s[i1], make_float2(cs, sn));
            s[i0] = make_float2(u.x + v.x, u.y + v.y);
            s[i1] = make_float2(u.x - v.x, u.y - v.y);
        }
        __syncthreads();
    }
    float* ph = g_phase + (size_t)row * TT;
    for (int t = tid; t < TT; t += blockDim.x)
        ph[t] = atan2f(s[t].y, s[t].x);
}

// ---------------- kernel 2: fused features + HMMA distance GEMM + argmin ----
__global__ void __launch_bounds__(256, 1)
quant_kernel(const float* __restrict__ imu,
             const float* __restrict__ Wm,
             const float* __restrict__ bm,
             const float* __restrict__ Wp,
             const float* __restrict__ bp,
             const float* __restrict__ cb,
             float* __restrict__ out) {
    extern __shared__ char smem[];
    const uint32_t sbase = smem_to_u32(smem);
    const int tid = threadIdx.x;
    const int wid = tid >> 5;
    const int lane = tid & 31;
    const int pbase = blockIdx.x * MBLK;

    float* scn = (float*)(smem + SM_CN);
    int* sidx = (int*)(smem + SM_IDX);

    for (int i = tid; i < NC; i += 256) scn[i] = g_cn[i];

    // ---- features for 128 positions -> SMEM A (bf16 split, rows 400 B)
    if (tid < MBLK) {
        const int p = pbase + tid;
        const int b = p >> 12;
        const int t = p & (TT - 1);

        const float* xb = imu + (size_t)b * CC * TT + t;
        float xc[9];
#pragma unroll
        for (int c = 0; c < 9; ++c) xc[c] = xb[c * TT];

        const float* phb = g_phase + (size_t)b * CC * TT + t;
        float pm = 0.0f;
#pragma unroll
        for (int c = 0; c < 9; ++c) pm += phb[c * TT];
        pm *= (1.0f / 9.0f);
        float sp, cp;
        sincosf(pm, &sp, &cp);
        out[OFF_PH + p] = pm;

        float f[64];
#pragma unroll
        for (int i = 0; i < 32; ++i) {
            float a = bm[i];
#pragma unroll
            for (int c = 0; c < 9; ++c) a += Wm[i * 9 + c] * xc[c];
            f[i] = a;
        }
        float comb[9];
#pragma unroll
        for (int c = 0; c < 7; ++c) comb[c] = xc[c];
        comb[7] = cp;
        comb[8] = sp;
#pragma unroll
        for (int i = 0; i < 32; ++i) {
            float a = bp[i];
#pragma unroll
            for (int c = 0; c < 9; ++c) a += Wp[i * 9 + c] * comb[c];
            f[32 + i] = a;
        }

        uint32_t* row32 = (uint32_t*)(smem + SM_A + (uint32_t)tid * KP_B);
#pragma unroll
        for (int q = 0; q < 32; ++q) {
            float v0 = f[2 * q], v1 = f[2 * q + 1];
            __nv_bfloat16 h0 = __float2bfloat16(v0), h1 = __float2bfloat16(v1);
            __nv_bfloat16 l0 = __float2bfloat16(v0 - __bfloat162float(h0));
            __nv_bfloat16 l1 = __float2bfloat16(v1 - __bfloat162float(h1));
            uint32_t hp = ((uint32_t)__bfloat16_as_ushort(h1) << 16) | __bfloat16_as_ushort(h0);
            uint32_t lp = ((uint32_t)__bfloat16_as_ushort(l1) << 16) | __bfloat16_as_ushort(l0);
            row32[q] = hp;            // seg0: f_hi
            row32[32 + q] = lp;       // seg1: f_lo
            row32[64 + q] = hp;       // seg2: f_hi
        }
    }
    __syncthreads();

    // ---- GEMM + argmin. Warp w: rows m0..m0+15, all 512 codes in 2 halves.
    const int m0 = wid * 16;
    float best_lo = CUDART_INF_F, best_hi = CUDART_INF_F;
    int idx_lo = 0, idx_hi = 0;

    // per-thread ldmatrix base addresses
    const int mgrp = lane >> 3;     // 0..3
    const int mrow = lane & 7;
    // A: M0 rows0-7@k, M1 rows8-15@k, M2 rows0-7@k+8, M3 rows8-15@k+8
    const uint32_t a_addr0 = sbase + SM_A
        + (uint32_t)(m0 + mrow + 8 * (mgrp & 1)) * KP_B
        + (uint32_t)(8 * (mgrp >> 1)) * 2u;
    // B: M0 codes0-7@k, M1 codes0-7@k+8, M2 codes8-15@k, M3 codes8-15@k+8
    const uint32_t b_row_off = (uint32_t)(8 * (mgrp >> 1) + mrow) * KP_B
        + (uint32_t)(8 * (mgrp & 1)) * 2u;

#pragma unroll 1
    for (int h = 0; h < 2; ++h) {
        // load B half: 256 codes x 24 uint4 (coalesced reads)
        {
            const uint4* src = (const uint4*)(g_B + (size_t)h * 256 * KTOT);
            for (int i = tid; i < 256 * 24; i += 256) {
                const int row = i / 24;
                const int kq = i - row * 24;
                *(uint4*)(smem + SM_B + (uint32_t)row * KP_B + (uint32_t)kq * 16u) = src[i];
            }
        }
        __syncthreads();

#pragma unroll 1
        for (int sub = 0; sub < 4; ++sub) {
            const int n0 = sub * 64;
            float acc[8][4];
#pragma unroll
            for (int t = 0; t < 8; ++t)
#pragma unroll
                for (int j = 0; j < 4; ++j) acc[t][j] = 0.0f;

#pragma unroll
            for (int ks = 0; ks < 12; ++ks) {
                const uint32_t koff = (uint32_t)(ks * 16) * 2u;
                uint32_t a[4];
                LDSM_X4(a[0], a[1], a[2], a[3], a_addr0 + koff);
                uint32_t bq[4][4];
#pragma unroll
                for (int j = 0; j < 4; ++j) {
                    const uint32_t baddr = sbase + SM_B
                        + (uint32_t)(n0 + 16 * j) * KP_B + b_row_off + koff;
                    LDSM_X4(bq[j][0], bq[j][1], bq[j][2], bq[j][3], baddr);
                }
#pragma unroll
                for (int j = 0; j < 4; ++j) {
                    MMA16816(acc[2 * j],     a, bq[j][0], bq[j][1]);
                    MMA16816(acc[2 * j + 1], a, bq[j][2], bq[j][3]);
                }
            }

            // epilogue: running argmin (codes strictly increasing -> first-min)
#pragma unroll
            for (int t = 0; t < 8; ++t) {
                const int c0 = h * 256 + n0 + 8 * t + (lane & 3) * 2;
                const float d0 = fmaf(-2.0f, acc[t][0], scn[c0]);
                const float d1 = fmaf(-2.0f, acc[t][1], scn[c0 + 1]);
                const float d2 = fmaf(-2.0f, acc[t][2], scn[c0]);
                const float d3 = fmaf(-2.0f, acc[t][3], scn[c0 + 1]);
                if (d0 < best_lo) { best_lo = d0; idx_lo = c0; }
                if (d1 < best_lo) { best_lo = d1; idx_lo = c0 + 1; }
                if (d2 < best_hi) { best_hi = d2; idx_hi = c0; }
                if (d3 < best_hi) { best_hi = d3; idx_hi = c0 + 1; }
            }
        }
        __syncthreads();   // before next half overwrites sB
    }

    // reduce across the 4 lanes sharing each row (lanes 4q..4q+3)
#pragma unroll
    for (int off = 1; off <= 2; off <<= 1) {
        float ob = __shfl_xor_sync(0xffffffffu, best_lo, off);
        int oi = __shfl_xor_sync(0xffffffffu, idx_lo, off);
        if (ob < best_lo || (ob == best_lo && oi < idx_lo)) { best_lo = ob; idx_lo = oi; }
        ob = __shfl_xor_sync(0xffffffffu, best_hi, off);
        oi = __shfl_xor_sync(0xffffffffu, idx_hi, off);
        if (ob < best_hi || (ob == best_hi && oi < idx_hi)) { best_hi = ob; idx_hi = oi; }
    }
    if ((lane & 3) == 0) {
        const int r = lane >> 2;
        sidx[m0 + r] = idx_lo;
        sidx[m0 + 8 + r] = idx_hi;
        out[OFF_IDX + pbase + m0 + r] = (float)idx_lo;
        out[OFF_IDX + pbase + m0 + 8 + r] = (float)idx_hi;
    }
    __syncthreads();

    // quantized rows from fp32 codebook (L2-hot)
    const float4* cb4 = (const float4*)cb;
    for (int q = tid; q < MBLK * (CD / 4); q += 256) {
        const int pos = q >> 4;
        const int w = q & 15;
        ((float4*)(out + (size_t)(pbase + pos) * CD))[w] =
            cb4[(size_t)sidx[pos] * (CD / 4) + w];
    }
}

// ---------------- launch ----------------
extern "C" void kernel_launch(void* const* d_in, const int* in_sizes, int n_in,
                              void* d_out, int out_size) {
    const float* imu = (const float*)d_in[0];
    const float* Wm  = (const float*)d_in[1];
    const float* bm  = (const float*)d_in[2];
    const float* Wp  = (const float*)d_in[3];
    const float* bp  = (const float*)d_in[4];
    const float* cb  = (const float*)d_in[5];
    float* out = (float*)d_out;

    convert_cb_kernel<<<2, 256>>>(cb);
    fft_phase_kernel<<<BB * CC, 256>>>(imu);

    cudaFuncSetAttribute(quant_kernel,
                         cudaFuncAttributeMaxDynamicSharedMemorySize, SMEMSZ);
    quant_kernel<<<(BB * TT) / MBLK, 256, SMEMSZ>>>(imu, Wm, bm, Wp, bp, cb, out);
}

// round 5
// speedup vs baseline: 2.5298x; 1.0924x over previous
#include <cuda_runtime.h>
#include <cuda_bf16.h>
#include <math_constants.h>
#include <cstdint>

#define BB 32
#define CC 9
#define TT 4096
#define NC 512
#define CD 64
#define KTOT 192          // hi | lo | hi split-K
#define MBLK 256          // positions per block
#define KP_B 400          // padded SMEM row stride in bytes (200 bf16)
#define QROWS 128         // codes per quarter

#define OFF_IDX ((size_t)BB * TT * CD)
#define OFF_PH  (OFF_IDX + (size_t)BB * TT)

// SMEM map (bytes)
#define SM_A   0u
#define SM_B0  102400u
#define SM_B1  153600u
#define SM_CN  204800u
#define SM_IDX 206848u
#define SMEMSZ 207872

// ---------------- global scratch ----------------
__device__ float g_phase[BB * CC * TT];
__device__ __align__(16) __nv_bfloat16 g_B[NC * KTOT];   // segs (hi,hi,lo)
__device__ float g_cn[NC];

__device__ __forceinline__ uint32_t smem_to_u32(const void* p) {
    uint32_t a;
    asm("{ .reg .u64 t; cvta.to.shared.u64 t, %1; cvt.u32.u64 %0, t; }"
        : "=r"(a) : "l"(p));
    return a;
}

#define LDSM_X4(r0, r1, r2, r3, addr) \
    asm volatile("ldmatrix.sync.aligned.m8n8.x4.shared.b16 {%0,%1,%2,%3}, [%4];" \
                 : "=r"(r0), "=r"(r1), "=r"(r2), "=r"(r3) : "r"(addr))

#define MMA16816(d, a, b0, b1) \
    asm volatile("mma.sync.aligned.m16n8k16.row.col.f32.bf16.bf16.f32 " \
                 "{%0,%1,%2,%3}, {%4,%5,%6,%7}, {%8,%9}, {%0,%1,%2,%3};" \
                 : "+f"((d)[0]), "+f"((d)[1]), "+f"((d)[2]), "+f"((d)[3]) \
                 : "r"((a)[0]), "r"((a)[1]), "r"((a)[2]), "r"((a)[3]), \
                   "r"(b0), "r"(b1))

#define CP_ASYNC16(saddr, gptr) \
    asm volatile("cp.async.cg.shared.global [%0], [%1], 16;" \
                 :: "r"(saddr), "l"(gptr) : "memory")
#define CP_COMMIT() asm volatile("cp.async.commit_group;" ::: "memory")
#define CP_WAIT(n)  asm volatile("cp.async.wait_group %0;" :: "n"(n) : "memory")

__device__ __forceinline__ float2 cmulf(float2 a, float2 b) {
    return make_float2(a.x * b.x - a.y * b.y, a.x * b.y + a.y * b.x);
}

__device__ __forceinline__ void split_pack(float v0, float v1,
                                           uint32_t& hp, uint32_t& lp) {
    __nv_bfloat16 h0 = __float2bfloat16(v0), h1 = __float2bfloat16(v1);
    __nv_bfloat16 l0 = __float2bfloat16(v0 - __bfloat162float(h0));
    __nv_bfloat16 l1 = __float2bfloat16(v1 - __bfloat162float(h1));
    hp = ((uint32_t)__bfloat16_as_ushort(h1) << 16) | __bfloat16_as_ushort(h0);
    lp = ((uint32_t)__bfloat16_as_ushort(l1) << 16) | __bfloat16_as_ushort(l0);
}

// ---------------- kernel 0: codebook -> bf16 split + norms (warp/code) ----
__global__ void convert_cb_kernel(const float* __restrict__ cb) {
    const int wid = threadIdx.x >> 5, lane = threadIdx.x & 31;
    const int c = blockIdx.x * 8 + wid;
    const float2 v = ((const float2*)(cb + (size_t)c * CD))[lane];
    float n = v.x * v.x + v.y * v.y;
    uint32_t hp, lp;
    split_pack(v.x, v.y, hp, lp);
    uint32_t* row32 = (uint32_t*)(g_B + (size_t)c * KTOT);
    row32[lane] = hp;
    row32[32 + lane] = hp;
    row32[64 + lane] = lp;
#pragma unroll
    for (int off = 16; off >= 1; off >>= 1)
        n += __shfl_xor_sync(0xffffffffu, n, off);
    if (lane == 0) g_cn[c] = n;
}

// ---------------- kernel 1: FFT phase with twiddle table ----------------
__global__ void fft_phase_kernel(const float* __restrict__ imu) {
    __shared__ float2 s[TT];        // 32 KB
    __shared__ float2 tw[TT / 2];   // 16 KB: tw[k] = exp(-i*pi*k/2048)
    const int row = blockIdx.x;
    const float* x = imu + (size_t)row * TT;
    const int tid = threadIdx.x;

    for (int k = tid; k < TT / 2; k += blockDim.x) {
        float sn, cs;
        sincosf(-(float)CUDART_PI_F * (float)k / (float)(TT / 2), &sn, &cs);
        tw[k] = make_float2(cs, sn);
    }
    for (int t = tid; t < TT; t += blockDim.x)
        s[t] = make_float2(x[t], 0.0f);
    __syncthreads();

    // Forward DIF: natural in, bit-reversed out.
    for (int lg = 11; lg >= 0; --lg) {
        const int len = 1 << lg;
        for (int i = tid; i < TT / 2; i += blockDim.x) {
            const int j = i & (len - 1);
            const int base = (i >> lg) << (lg + 1);
            const int i0 = base + j, i1 = i0 + len;
            float2 u = s[i0], v = s[i1];
            float2 w = tw[j << (11 - lg)];
            s[i0] = make_float2(u.x + v.x, u.y + v.y);
            float2 d = make_float2(u.x - v.x, u.y - v.y);
            s[i1] = cmulf(d, w);
        }
        __syncthreads();
    }
    // Hilbert multiplier at bit-reversed slot.
    for (int p = tid; p < TT; p += blockDim.x) {
        const int k = (int)(__brev((unsigned)p) >> 20);
        float h;
        if (k == 0 || k == TT / 2) h = 1.0f;
        else if (k < TT / 2)       h = 2.0f;
        else                       h = 0.0f;
        s[p].x *= h;
        s[p].y *= h;
    }
    __syncthreads();
    // Inverse DIT: bit-reversed in, natural out (conjugate twiddles, no 1/N).
    for (int lg = 0; lg <= 11; ++lg) {
        const int len = 1 << lg;
        for (int i = tid; i < TT / 2; i += blockDim.x) {
            const int j = i & (len - 1);
            const int base = (i >> lg) << (lg + 1);
            const int i0 = base + j, i1 = i0 + len;
            float2 w = tw[j << (11 - lg)];
            float2 u = s[i0];
            float2 v = cmulf(s[i1], make_float2(w.x, -w.y));
            s[i0] = make_float2(u.x + v.x, u.y + v.y);
            s[i1] = make_float2(u.x - v.x, u.y - v.y);
        }
        __syncthreads();
    }
    float* ph = g_phase + (size_t)row * TT;
    for (int t = tid; t < TT; t += blockDim.x)
        ph[t] = atan2f(s[t].y, s[t].x);
}

// ---------------- kernel 2: fused features + HMMA GEMM + argmin ----------
__device__ __forceinline__ void prefetch_quarter(uint32_t sdst, int qt, int tid) {
    const char* src = (const char*)g_B + (size_t)qt * QROWS * KTOT * 2;
#pragma unroll
    for (int it = 0; it < 12; ++it) {
        const int i = tid + it * 256;       // 3072 uint4 total
        const int r = i / 24, kq = i - r * 24;
        CP_ASYNC16(sdst + (uint32_t)r * KP_B + (uint32_t)kq * 16u,
                   src + (size_t)r * 384 + (size_t)kq * 16);
    }
    CP_COMMIT();
}

__global__ void __launch_bounds__(256, 1)
quant_kernel(const float* __restrict__ imu,
             const float* __restrict__ Wm,
             const float* __restrict__ bm,
             const float* __restrict__ Wp,
             const float* __restrict__ bp,
             const float* __restrict__ cb,
             float* __restrict__ out) {
    extern __shared__ char smem[];
    const uint32_t sbase = smem_to_u32(smem);
    const int tid = threadIdx.x;
    const int wid = tid >> 5;
    const int lane = tid & 31;
    const int pbase = blockIdx.x * MBLK;

    float* scn = (float*)(smem + SM_CN);
    int* sidx = (int*)(smem + SM_IDX);

    // start B pipeline before the heavy feature phase
    prefetch_quarter(sbase + SM_B0, 0, tid);
    prefetch_quarter(sbase + SM_B1, 1, tid);

    for (int i = tid; i < NC; i += 256) scn[i] = g_cn[i];

    // ---- features: one position per thread -> SMEM A (bf16 split)
    {
        const int p = pbase + tid;
        const int b = p >> 12;
        const int t = p & (TT - 1);

        const float* xb = imu + (size_t)b * CC * TT + t;
        float xc[9];
#pragma unroll
        for (int c = 0; c < 9; ++c) xc[c] = xb[c * TT];

        const float* phb = g_phase + (size_t)b * CC * TT + t;
        float pm = 0.0f;
#pragma unroll
        for (int c = 0; c < 9; ++c) pm += phb[c * TT];
        pm *= (1.0f / 9.0f);
        float sp, cp;
        sincosf(pm, &sp, &cp);
        out[OFF_PH + p] = pm;

        float f[64];
#pragma unroll
        for (int i = 0; i < 32; ++i) {
            float a = bm[i];
#pragma unroll
            for (int c = 0; c < 9; ++c) a += Wm[i * 9 + c] * xc[c];
            f[i] = a;
        }
        float comb[9];
#pragma unroll
        for (int c = 0; c < 7; ++c) comb[c] = xc[c];
        comb[7] = cp;
        comb[8] = sp;
#pragma unroll
        for (int i = 0; i < 32; ++i) {
            float a = bp[i];
#pragma unroll
            for (int c = 0; c < 9; ++c) a += Wp[i * 9 + c] * comb[c];
            f[32 + i] = a;
        }

        uint32_t* row32 = (uint32_t*)(smem + SM_A + (uint32_t)tid * KP_B);
#pragma unroll
        for (int q = 0; q < 32; ++q) {
            uint32_t hp, lp;
            split_pack(f[2 * q], f[2 * q + 1], hp, lp);
            row32[q] = hp;            // seg0: f_hi
            row32[32 + q] = lp;       // seg1: f_lo
            row32[64 + q] = hp;       // seg2: f_hi
        }
    }
    __syncthreads();   // A + cn visible

    // ---- GEMM + argmin. Warp w: rows m0..m0+31, codes in 4 quarters of 128.
    const int m0 = wid * 32;
    float best[2][2];
    int bidx[2][2];
#pragma unroll
    for (int mt = 0; mt < 2; ++mt) {
        best[mt][0] = CUDART_INF_F; best[mt][1] = CUDART_INF_F;
        bidx[mt][0] = 0; bidx[mt][1] = 0;
    }

    const int mgrp = lane >> 3;     // 0..3
    const int mrow = lane & 7;
    const uint32_t a_base0 = sbase + SM_A
        + (uint32_t)(m0 + mrow + 8 * (mgrp & 1)) * KP_B
        + (uint32_t)(8 * (mgrp >> 1)) * 2u;
    const uint32_t a_base1 = a_base0 + 16u * KP_B;
    const uint32_t b_row_off = (uint32_t)(8 * (mgrp >> 1) + mrow) * KP_B
        + (uint32_t)(8 * (mgrp & 1)) * 2u;

#pragma unroll
    for (int qt = 0; qt < 4; ++qt) {
        if (qt < 3) { CP_WAIT(1); } else { CP_WAIT(0); }
        __syncthreads();            // quarter buffer complete for all warps

        const uint32_t sB = sbase + ((qt & 1) ? SM_B1 : SM_B0);

#pragma unroll 1
        for (int sub = 0; sub < 2; ++sub) {
            const int n0 = sub * 64;
            float acc[2][8][4];
#pragma unroll
            for (int mt = 0; mt < 2; ++mt)
#pragma unroll
                for (int t = 0; t < 8; ++t)
#pragma unroll
                    for (int j = 0; j < 4; ++j) acc[mt][t][j] = 0.0f;

#pragma unroll
            for (int ks = 0; ks < 12; ++ks) {
                const uint32_t koff = (uint32_t)ks * 32u;
                uint32_t a0[4], a1[4];
                LDSM_X4(a0[0], a0[1], a0[2], a0[3], a_base0 + koff);
                LDSM_X4(a1[0], a1[1], a1[2], a1[3], a_base1 + koff);
#pragma unroll
                for (int j = 0; j < 4; ++j) {
                    uint32_t bq0, bq1, bq2, bq3;
                    LDSM_X4(bq0, bq1, bq2, bq3,
                            sB + (uint32_t)(n0 + 16 * j) * KP_B + b_row_off + koff);
                    MMA16816(acc[0][2 * j],     a0, bq0, bq1);
                    MMA16816(acc[0][2 * j + 1], a0, bq2, bq3);
                    MMA16816(acc[1][2 * j],     a1, bq0, bq1);
                    MMA16816(acc[1][2 * j + 1], a1, bq2, bq3);
                }
            }

            // running argmin (codes strictly increasing -> first-min kept)
#pragma unroll
            for (int t = 0; t < 8; ++t) {
                const int c0 = qt * QROWS + n0 + 8 * t + (lane & 3) * 2;
                const float n0v = scn[c0], n1v = scn[c0 + 1];
#pragma unroll
                for (int mt = 0; mt < 2; ++mt) {
                    const float d0 = fmaf(-2.0f, acc[mt][t][0], n0v);
                    const float d1 = fmaf(-2.0f, acc[mt][t][1], n1v);
                    const float d2 = fmaf(-2.0f, acc[mt][t][2], n0v);
                    const float d3 = fmaf(-2.0f, acc[mt][t][3], n1v);
                    if (d0 < best[mt][0]) { best[mt][0] = d0; bidx[mt][0] = c0; }
                    if (d1 < best[mt][0]) { best[mt][0] = d1; bidx[mt][0] = c0 + 1; }
                    if (d2 < best[mt][1]) { best[mt][1] = d2; bidx[mt][1] = c0; }
                    if (d3 < best[mt][1]) { best[mt][1] = d3; bidx[mt][1] = c0 + 1; }
                }
            }
        }
        __syncthreads();            // all warps done reading this buffer
        if (qt < 2) prefetch_quarter(sbase + ((qt & 1) ? SM_B1 : SM_B0),
                                     qt + 2, tid);
    }

    // reduce across the 4 lanes sharing each row
#pragma unroll
    for (int off = 1; off <= 2; off <<= 1) {
#pragma unroll
        for (int mt = 0; mt < 2; ++mt)
#pragma unroll
            for (int hh = 0; hh < 2; ++hh) {
                float ob = __shfl_xor_sync(0xffffffffu, best[mt][hh], off);
                int oi = __shfl_xor_sync(0xffffffffu, bidx[mt][hh], off);
                if (ob < best[mt][hh] || (ob == best[mt][hh] && oi < bidx[mt][hh])) {
                    best[mt][hh] = ob; bidx[mt][hh] = oi;
                }
            }
    }
    if ((lane & 3) == 0) {
        const int r = lane >> 2;
#pragma unroll
        for (int mt = 0; mt < 2; ++mt) {
            const int row_lo = m0 + 16 * mt + r;
            const int row_hi = row_lo + 8;
            sidx[row_lo] = bidx[mt][0];
            sidx[row_hi] = bidx[mt][1];
            out[OFF_IDX + pbase + row_lo] = (float)bidx[mt][0];
            out[OFF_IDX + pbase + row_hi] = (float)bidx[mt][1];
        }
    }
    __syncthreads();

    // quantized rows from fp32 codebook (L2-hot)
    const float4* cb4 = (const float4*)cb;
    for (int q = tid; q < MBLK * (CD / 4); q += 256) {
        const int pos = q >> 4;
        const int w = q & 15;
        ((float4*)(out + (size_t)(pbase + pos) * CD))[w] =
            cb4[(size_t)sidx[pos] * (CD / 4) + w];
    }
}

// ---------------- launch ----------------
extern "C" void kernel_launch(void* const* d_in, const int* in_sizes, int n_in,
                              void* d_out, int out_size) {
    const float* imu = (const float*)d_in[0];
    const float* Wm  = (const float*)d_in[1];
    const float* bm  = (const float*)d_in[2];
    const float* Wp  = (const float*)d_in[3];
    const float* bp  = (const float*)d_in[4];
    const float* cb  = (const float*)d_in[5];
    float* out = (float*)d_out;

    convert_cb_kernel<<<NC / 8, 256>>>(cb);
    fft_phase_kernel<<<BB * CC, 256>>>(imu);

    cudaFuncSetAttribute(quant_kernel,
                         cudaFuncAttributeMaxDynamicSharedMemorySize, SMEMSZ);
    quant_kernel<<<(BB * TT) / MBLK, 256, SMEMSZ>>>(imu, Wm, bm, Wp, bp, cb, out);
}

// round 6
// speedup vs baseline: 2.6642x; 1.0531x over previous
#include <cuda_runtime.h>
#include <cuda_bf16.h>
#include <math_constants.h>
#include <cstdint>

#define BB 32
#define CC 9
#define TT 4096
#define NC 512
#define CD 64
#define KTOT 192          // hi | lo | hi split-K
#define MBLK 128          // positions per block
#define KP_B 400          // padded SMEM row stride in bytes (200 bf16)
#define CROWS 64          // codes per chunk (8 chunks)

#define OFF_IDX ((size_t)BB * TT * CD)
#define OFF_PH  (OFF_IDX + (size_t)BB * TT)

// SMEM map for quant kernel (bytes)
#define SM_A   0u
#define SM_B0  51200u
#define SM_B1  76800u
#define SM_CN  102400u
#define SM_IDX 104448u
#define SMEMSZ 104960     // <= 113 KB -> 2 CTAs/SM

// ---------------- global scratch ----------------
__device__ float g_phase[BB * CC * TT];
__device__ __align__(16) __nv_bfloat16 g_B[NC * KTOT];   // segs (hi,hi,lo)
__device__ float g_cn[NC];

__device__ __forceinline__ uint32_t smem_to_u32(const void* p) {
    uint32_t a;
    asm("{ .reg .u64 t; cvta.to.shared.u64 t, %1; cvt.u32.u64 %0, t; }"
        : "=r"(a) : "l"(p));
    return a;
}

#define LDSM_X4(r0, r1, r2, r3, addr) \
    asm volatile("ldmatrix.sync.aligned.m8n8.x4.shared.b16 {%0,%1,%2,%3}, [%4];" \
                 : "=r"(r0), "=r"(r1), "=r"(r2), "=r"(r3) : "r"(addr))

#define MMA16816(d, a, b0, b1) \
    asm volatile("mma.sync.aligned.m16n8k16.row.col.f32.bf16.bf16.f32 " \
                 "{%0,%1,%2,%3}, {%4,%5,%6,%7}, {%8,%9}, {%0,%1,%2,%3};" \
                 : "+f"((d)[0]), "+f"((d)[1]), "+f"((d)[2]), "+f"((d)[3]) \
                 : "r"((a)[0]), "r"((a)[1]), "r"((a)[2]), "r"((a)[3]), \
                   "r"(b0), "r"(b1))

#define CP_ASYNC16(saddr, gptr) \
    asm volatile("cp.async.cg.shared.global [%0], [%1], 16;" \
                 :: "r"(saddr), "l"(gptr) : "memory")
#define CP_COMMIT() asm volatile("cp.async.commit_group;" ::: "memory")
#define CP_WAIT(n)  asm volatile("cp.async.wait_group %0;" :: "n"(n) : "memory")

__device__ __forceinline__ float2 cmulf(float2 a, float2 b) {
    return make_float2(a.x * b.x - a.y * b.y, a.x * b.y + a.y * b.x);
}
__device__ __forceinline__ float2 f2add(float2 a, float2 b) {
    return make_float2(a.x + b.x, a.y + b.y);
}
__device__ __forceinline__ float2 f2sub(float2 a, float2 b) {
    return make_float2(a.x - b.x, a.y - b.y);
}

__device__ __forceinline__ void split_pack(float v0, float v1,
                                           uint32_t& hp, uint32_t& lp) {
    __nv_bfloat16 h0 = __float2bfloat16(v0), h1 = __float2bfloat16(v1);
    __nv_bfloat16 l0 = __float2bfloat16(v0 - __bfloat162float(h0));
    __nv_bfloat16 l1 = __float2bfloat16(v1 - __bfloat162float(h1));
    hp = ((uint32_t)__bfloat16_as_ushort(h1) << 16) | __bfloat16_as_ushort(h0);
    lp = ((uint32_t)__bfloat16_as_ushort(l1) << 16) | __bfloat16_as_ushort(l0);
}

// ---------------- kernel 1: radix-4 FFT phase + fused codebook convert ----
// blocks [0, 288): one (b,c) row each. blocks [288, 352): codebook convert.
__global__ void fft_conv_kernel(const float* __restrict__ imu,
                                const float* __restrict__ cb) {
    const int tid = threadIdx.x;

    if (blockIdx.x >= BB * CC) {
        // ---- codebook convert: warp per code ----
        const int wid = tid >> 5, lane = tid & 31;
        const int c = (blockIdx.x - BB * CC) * 8 + wid;
        const float2 v = ((const float2*)(cb + (size_t)c * CD))[lane];
        float n = v.x * v.x + v.y * v.y;
        uint32_t hp, lp;
        split_pack(v.x, v.y, hp, lp);
        uint32_t* row32 = (uint32_t*)(g_B + (size_t)c * KTOT);
        row32[lane] = hp;
        row32[32 + lane] = hp;
        row32[64 + lane] = lp;
#pragma unroll
        for (int off = 16; off >= 1; off >>= 1)
            n += __shfl_xor_sync(0xffffffffu, n, off);
        if (lane == 0) g_cn[c] = n;
        return;
    }

    extern __shared__ float2 dsh[];
    float2* s = dsh;            // 4096
    float2* tw = dsh + TT;      // 4096: tw[k] = exp(-2*pi*i*k/4096)
    const int row = blockIdx.x;
    const float* x = imu + (size_t)row * TT;

    for (int k = tid; k < TT; k += 256) {
        float sn, cs;
        sincosf(-(float)CUDART_PI_F * (float)k / 2048.0f, &sn, &cs);
        tw[k] = make_float2(cs, sn);
    }
    for (int t = tid; t < TT; t += 256)
        s[t] = make_float2(x[t], 0.0f);
    __syncthreads();

    // Forward radix-4 DIF: natural in, base-4 digit-reversed out.
#pragma unroll
    for (int ls = 10; ls >= 0; ls -= 2) {
        const int L = 1 << ls;
        const int m = 1024 >> ls;
        for (int i = tid; i < 1024; i += 256) {
            const int j = i & (L - 1);
            const int i0 = ((i >> ls) << (ls + 2)) + j;
            float2 a = s[i0], b = s[i0 + L], c = s[i0 + 2 * L], d = s[i0 + 3 * L];
            float2 t0 = f2add(a, c), t1 = f2sub(a, c);
            float2 t2 = f2add(b, d), t3 = f2sub(b, d);
            s[i0] = f2add(t0, t2);
            s[i0 + L] = cmulf(make_float2(t1.x + t3.y, t1.y - t3.x), tw[j * m]);
            s[i0 + 2 * L] = cmulf(f2sub(t0, t2), tw[2 * j * m]);
            s[i0 + 3 * L] = cmulf(make_float2(t1.x - t3.y, t1.y + t3.x), tw[3 * j * m]);
        }
        __syncthreads();
    }

    // Hilbert multiplier h[k] applied at base-4 digit-reversed slot.
    for (int p = tid; p < TT; p += 256) {
        const int r = (int)(__brev((unsigned)p) >> 20);         // 12-bit reverse
        const int k = ((r & 0x555) << 1) | ((r >> 1) & 0x555);  // swap bit pairs
        float h;
        if (k == 0 || k == TT / 2) h = 1.0f;
        else if (k < TT / 2)       h = 2.0f;
        else                       h = 0.0f;
        s[p].x *= h;
        s[p].y *= h;
    }
    __syncthreads();

    // Inverse radix-4 DIT: digit-reversed in, natural out (conj twiddles, no 1/N).
#pragma unroll
    for (int ls = 0; ls <= 10; ls += 2) {
        const int L = 1 << ls;
        const int m = 1024 >> ls;
        for (int i = tid; i < 1024; i += 256) {
            const int j = i & (L - 1);
            const int i0 = ((i >> ls) << (ls + 2)) + j;
            float2 w1 = tw[j * m], w2 = tw[2 * j * m], w3 = tw[3 * j * m];
            float2 A = s[i0];
            float2 Bv = cmulf(s[i0 + L],     make_float2(w1.x, -w1.y));
            float2 Cv = cmulf(s[i0 + 2 * L], make_float2(w2.x, -w2.y));
            float2 Dv = cmulf(s[i0 + 3 * L], make_float2(w3.x, -w3.y));
            float2 t0 = f2add(A, Cv), t1 = f2sub(A, Cv);
            float2 t2 = f2add(Bv, Dv), t3 = f2sub(Bv, Dv);
            s[i0] = f2add(t0, t2);
            s[i0 + L] = make_float2(t1.x - t3.y, t1.y + t3.x);
            s[i0 + 2 * L] = f2sub(t0, t2);
            s[i0 + 3 * L] = make_float2(t1.x + t3.y, t1.y - t3.x);
        }
        __syncthreads();
    }

    float* ph = g_phase + (size_t)row * TT;
    for (int t = tid; t < TT; t += 256)
        ph[t] = atan2f(s[t].y, s[t].x);
}

// ---------------- kernel 2: fused features + HMMA GEMM + argmin ----------
__device__ __forceinline__ void prefetch_chunk(uint32_t sdst, int ch, int tid) {
    const char* src = (const char*)g_B + (size_t)ch * CROWS * KTOT * 2;
#pragma unroll
    for (int it = 0; it < 6; ++it) {
        const int i = tid + it * 256;       // 1536 uint4 total
        const int r = i / 24, kq = i - r * 24;
        CP_ASYNC16(sdst + (uint32_t)r * KP_B + (uint32_t)kq * 16u,
                   src + (size_t)r * 384 + (size_t)kq * 16);
    }
    CP_COMMIT();
}

__global__ void __launch_bounds__(256, 2)
quant_kernel(const float* __restrict__ imu,
             const float* __restrict__ Wm,
             const float* __restrict__ bm,
             const float* __restrict__ Wp,
             const float* __restrict__ bp,
             const float* __restrict__ cb,
             float* __restrict__ out) {
    extern __shared__ char smem[];
    const uint32_t sbase = smem_to_u32(smem);
    const int tid = threadIdx.x;
    const int wid = tid >> 5;
    const int lane = tid & 31;
    const int pbase = blockIdx.x * MBLK;

    float* scn = (float*)(smem + SM_CN);
    int* sidx = (int*)(smem + SM_IDX);

    // start B pipeline before the heavy feature phase
    prefetch_chunk(sbase + SM_B0, 0, tid);
    prefetch_chunk(sbase + SM_B1, 1, tid);

    for (int i = tid; i < NC; i += 256) scn[i] = g_cn[i];

    // ---- features for 128 positions -> SMEM A (bf16 split)
    if (tid < MBLK) {
        const int p = pbase + tid;
        const int b = p >> 12;
        const int t = p & (TT - 1);

        const float* xb = imu + (size_t)b * CC * TT + t;
        float xc[9];
#pragma unroll
        for (int c = 0; c < 9; ++c) xc[c] = xb[c * TT];

        const float* phb = g_phase + (size_t)b * CC * TT + t;
        float pm = 0.0f;
#pragma unroll
        for (int c = 0; c < 9; ++c) pm += phb[c * TT];
        pm *= (1.0f / 9.0f);
        float sp, cp;
        sincosf(pm, &sp, &cp);
        out[OFF_PH + p] = pm;

        float f[64];
#pragma unroll
        for (int i = 0; i < 32; ++i) {
            float a = bm[i];
#pragma unroll
            for (int c = 0; c < 9; ++c) a += Wm[i * 9 + c] * xc[c];
            f[i] = a;
        }
        float comb[9];
#pragma unroll
        for (int c = 0; c < 7; ++c) comb[c] = xc[c];
        comb[7] = cp;
        comb[8] = sp;
#pragma unroll
        for (int i = 0; i < 32; ++i) {
            float a = bp[i];
#pragma unroll
            for (int c = 0; c < 9; ++c) a += Wp[i * 9 + c] * comb[c];
            f[32 + i] = a;
        }

        uint32_t* row32 = (uint32_t*)(smem + SM_A + (uint32_t)tid * KP_B);
#pragma unroll
        for (int q = 0; q < 32; ++q) {
            uint32_t hp, lp;
            split_pack(f[2 * q], f[2 * q + 1], hp, lp);
            row32[q] = hp;            // seg0: f_hi
            row32[32 + q] = lp;       // seg1: f_lo
            row32[64 + q] = hp;       // seg2: f_hi
        }
    }
    __syncthreads();   // A + cn visible

    // ---- GEMM + argmin. Warp w: rows m0..m0+15, codes in 8 chunks of 64.
    const int m0 = wid * 16;
    float best_lo = CUDART_INF_F, best_hi = CUDART_INF_F;
    int idx_lo = 0, idx_hi = 0;

    const int mgrp = lane >> 3;     // 0..3
    const int mrow = lane & 7;
    const uint32_t a_addr0 = sbase + SM_A
        + (uint32_t)(m0 + mrow + 8 * (mgrp & 1)) * KP_B
        + (uint32_t)(8 * (mgrp >> 1)) * 2u;
    const uint32_t b_row_off = (uint32_t)(8 * (mgrp >> 1) + mrow) * KP_B
        + (uint32_t)(8 * (mgrp & 1)) * 2u;

#pragma unroll 1
    for (int ch = 0; ch < 8; ++ch) {
        if (ch < 7) { CP_WAIT(1); } else { CP_WAIT(0); }
        __syncthreads();            // chunk buffer complete for all warps

        const uint32_t sB = sbase + ((ch & 1) ? SM_B1 : SM_B0);

        float acc[8][4];
#pragma unroll
        for (int t = 0; t < 8; ++t)
#pragma unroll
            for (int j = 0; j < 4; ++j) acc[t][j] = 0.0f;

#pragma unroll
        for (int ks = 0; ks < 12; ++ks) {
            const uint32_t koff = (uint32_t)ks * 32u;
            uint32_t a[4];
            LDSM_X4(a[0], a[1], a[2], a[3], a_addr0 + koff);
#pragma unroll
            for (int j = 0; j < 4; ++j) {
                uint32_t bq0, bq1, bq2, bq3;
                LDSM_X4(bq0, bq1, bq2, bq3,
                        sB + (uint32_t)(16 * j) * KP_B + b_row_off + koff);
                MMA16816(acc[2 * j],     a, bq0, bq1);
                MMA16816(acc[2 * j + 1], a, bq2, bq3);
            }
        }

        // running argmin (codes strictly increasing -> first-min kept)
#pragma unroll
        for (int t = 0; t < 8; ++t) {
            const int c0 = ch * CROWS + 8 * t + (lane & 3) * 2;
            const float d0 = fmaf(-2.0f, acc[t][0], scn[c0]);
            const float d1 = fmaf(-2.0f, acc[t][1], scn[c0 + 1]);
            const float d2 = fmaf(-2.0f, acc[t][2], scn[c0]);
            const float d3 = fmaf(-2.0f, acc[t][3], scn[c0 + 1]);
            if (d0 < best_lo) { best_lo = d0; idx_lo = c0; }
            if (d1 < best_lo) { best_lo = d1; idx_lo = c0 + 1; }
            if (d2 < best_hi) { best_hi = d2; idx_hi = c0; }
            if (d3 < best_hi) { best_hi = d3; idx_hi = c0 + 1; }
        }

        __syncthreads();            // all warps done reading this buffer
        if (ch < 6) prefetch_chunk(sbase + ((ch & 1) ? SM_B1 : SM_B0),
                                   ch + 2, tid);
    }

    // reduce across the 4 lanes sharing each row
#pragma unroll
    for (int off = 1; off <= 2; off <<= 1) {
        float ob = __shfl_xor_sync(0xffffffffu, best_lo, off);
        int oi = __shfl_xor_sync(0xffffffffu, idx_lo, off);
        if (ob < best_lo || (ob == best_lo && oi < idx_lo)) { best_lo = ob; idx_lo = oi; }
        ob = __shfl_xor_sync(0xffffffffu, best_hi, off);
        oi = __shfl_xor_sync(0xffffffffu, idx_hi, off);
        if (ob < best_hi || (ob == best_hi && oi < idx_hi)) { best_hi = ob; idx_hi = oi; }
    }
    if ((lane & 3) == 0) {
        const int r = lane >> 2;
        sidx[m0 + r] = idx_lo;
        sidx[m0 + 8 + r] = idx_hi;
        out[OFF_IDX + pbase + m0 + r] = (float)idx_lo;
        out[OFF_IDX + pbase + m0 + 8 + r] = (float)idx_hi;
    }
    __syncthreads();

    // quantized rows from fp32 codebook (L2-hot)
    const float4* cb4 = (const float4*)cb;
    for (int q = tid; q < MBLK * (CD / 4); q += 256) {
        const int pos = q >> 4;
        const int w = q & 15;
        ((float4*)(out + (size_t)(pbase + pos) * CD))[w] =
            cb4[(size_t)sidx[pos] * (CD / 4) + w];
    }
}

// ---------------- launch ----------------
extern "C" void kernel_launch(void* const* d_in, const int* in_sizes, int n_in,
                              void* d_out, int out_size) {
    const float* imu = (const float*)d_in[0];
    const float* Wm  = (const float*)d_in[1];
    const float* bm  = (const float*)d_in[2];
    const float* Wp  = (const float*)d_in[3];
    const float* bp  = (const float*)d_in[4];
    const float* cb  = (const float*)d_in[5];
    float* out = (float*)d_out;

    const int fft_smem = 2 * TT * (int)sizeof(float2);  // 64 KB
    cudaFuncSetAttribute(fft_conv_kernel,
                         cudaFuncAttributeMaxDynamicSharedMemorySize, fft_smem);
    fft_conv_kernel<<<BB * CC + NC / 8, 256, fft_smem>>>(imu, cb);

    cudaFuncSetAttribute(quant_kernel,
                         cudaFuncAttributeMaxDynamicSharedMemorySize, SMEMSZ);
    quant_kernel<<<(BB * TT) / MBLK, 256, SMEMSZ>>>(imu, Wm, bm, Wp, bp, cb, out);
}

// round 7
// speedup vs baseline: 2.6722x; 1.0030x over previous
#include <cuda_runtime.h>
#include <cuda_bf16.h>
#include <math_constants.h>
#include <cstdint>

#define BB 32
#define CC 9
#define TT 4096
#define NC 512
#define CD 64
#define KTOT 192          // hi | lo | hi split-K
#define MBLK 128          // positions per block
#define KP_B 400          // padded SMEM row stride in bytes (200 bf16)
#define CROWS 64          // codes per chunk (8 chunks)

#define OFF_IDX ((size_t)BB * TT * CD)
#define OFF_PH  (OFF_IDX + (size_t)BB * TT)

// SMEM map for quant kernel (bytes)
#define SM_A    0u
#define SM_B0   51200u
#define SM_B1   76800u
#define SM_CN   102400u
#define SM_RBV  104448u   // float [128][4] per-warpcol best
#define SM_RBI  106496u   // int   [128][4] per-warpcol idx
#define SM_IDX  108544u   // int   [128]
#define SMEMSZ  109056    // 2 CTAs/SM

// ---------------- global scratch ----------------
__device__ float g_phase[BB * CC * TT];
__device__ __align__(16) __nv_bfloat16 g_B[NC * KTOT];   // segs (hi,hi,lo)
__device__ float g_cn[NC];

__device__ __forceinline__ uint32_t smem_to_u32(const void* p) {
    uint32_t a;
    asm("{ .reg .u64 t; cvta.to.shared.u64 t, %1; cvt.u32.u64 %0, t; }"
        : "=r"(a) : "l"(p));
    return a;
}

#define LDSM_X4(r0, r1, r2, r3, addr) \
    asm volatile("ldmatrix.sync.aligned.m8n8.x4.shared.b16 {%0,%1,%2,%3}, [%4];" \
                 : "=r"(r0), "=r"(r1), "=r"(r2), "=r"(r3) : "r"(addr))

#define MMA16816(d, a, b0, b1) \
    asm volatile("mma.sync.aligned.m16n8k16.row.col.f32.bf16.bf16.f32 " \
                 "{%0,%1,%2,%3}, {%4,%5,%6,%7}, {%8,%9}, {%0,%1,%2,%3};" \
                 : "+f"((d)[0]), "+f"((d)[1]), "+f"((d)[2]), "+f"((d)[3]) \
                 : "r"((a)[0]), "r"((a)[1]), "r"((a)[2]), "r"((a)[3]), \
                   "r"(b0), "r"(b1))

#define CP_ASYNC16(saddr, gptr) \
    asm volatile("cp.async.cg.shared.global [%0], [%1], 16;" \
                 :: "r"(saddr), "l"(gptr) : "memory")
#define CP_COMMIT() asm volatile("cp.async.commit_group;" ::: "memory")
#define CP_WAIT(n)  asm volatile("cp.async.wait_group %0;" :: "n"(n) : "memory")

__device__ __forceinline__ float2 cmulf(float2 a, float2 b) {
    return make_float2(a.x * b.x - a.y * b.y, a.x * b.y + a.y * b.x);
}
__device__ __forceinline__ float2 f2add(float2 a, float2 b) {
    return make_float2(a.x + b.x, a.y + b.y);
}
__device__ __forceinline__ float2 f2sub(float2 a, float2 b) {
    return make_float2(a.x - b.x, a.y - b.y);
}

__device__ __forceinline__ void split_pack(float v0, float v1,
                                           uint32_t& hp, uint32_t& lp) {
    __nv_bfloat16 h0 = __float2bfloat16(v0), h1 = __float2bfloat16(v1);
    __nv_bfloat16 l0 = __float2bfloat16(v0 - __bfloat162float(h0));
    __nv_bfloat16 l1 = __float2bfloat16(v1 - __bfloat162float(h1));
    hp = ((uint32_t)__bfloat16_as_ushort(h1) << 16) | __bfloat16_as_ushort(h0);
    lp = ((uint32_t)__bfloat16_as_ushort(l1) << 16) | __bfloat16_as_ushort(l0);
}

// ---------------- kernel 1: radix-4 FFT phase + fused codebook convert ----
// blocks [0, 288): one (b,c) row each (512 thr). blocks [288, 320): convert.
__global__ void fft_conv_kernel(const float* __restrict__ imu,
                                const float* __restrict__ cb) {
    const int tid = threadIdx.x;

    if (blockIdx.x >= BB * CC) {
        // ---- codebook convert: warp per code (16 warps) ----
        const int wid = tid >> 5, lane = tid & 31;
        const int c = (blockIdx.x - BB * CC) * 16 + wid;
        const float2 v = ((const float2*)(cb + (size_t)c * CD))[lane];
        float n = v.x * v.x + v.y * v.y;
        uint32_t hp, lp;
        split_pack(v.x, v.y, hp, lp);
        uint32_t* row32 = (uint32_t*)(g_B + (size_t)c * KTOT);
        row32[lane] = hp;
        row32[32 + lane] = hp;
        row32[64 + lane] = lp;
#pragma unroll
        for (int off = 16; off >= 1; off >>= 1)
            n += __shfl_xor_sync(0xffffffffu, n, off);
        if (lane == 0) g_cn[c] = n;
        return;
    }

    extern __shared__ float2 dsh[];
    float2* s = dsh;            // 4096
    float2* tw = dsh + TT;      // 4096: tw[k] = exp(-2*pi*i*k/4096)
    const int row = blockIdx.x;
    const float* x = imu + (size_t)row * TT;

    for (int k = tid; k < TT; k += 512) {
        float sn, cs;
        sincosf(-(float)CUDART_PI_F * (float)k / 2048.0f, &sn, &cs);
        tw[k] = make_float2(cs, sn);
    }
    for (int t = tid; t < TT; t += 512)
        s[t] = make_float2(x[t], 0.0f);
    __syncthreads();

    // Forward radix-4 DIF: natural in, base-4 digit-reversed out.
#pragma unroll
    for (int ls = 10; ls >= 0; ls -= 2) {
        const int L = 1 << ls;
        const int m = 1024 >> ls;
        for (int i = tid; i < 1024; i += 512) {
            const int j = i & (L - 1);
            const int i0 = ((i >> ls) << (ls + 2)) + j;
            float2 a = s[i0], b = s[i0 + L], c = s[i0 + 2 * L], d = s[i0 + 3 * L];
            float2 t0 = f2add(a, c), t1 = f2sub(a, c);
            float2 t2 = f2add(b, d), t3 = f2sub(b, d);
            s[i0] = f2add(t0, t2);
            s[i0 + L] = cmulf(make_float2(t1.x + t3.y, t1.y - t3.x), tw[j * m]);
            s[i0 + 2 * L] = cmulf(f2sub(t0, t2), tw[2 * j * m]);
            s[i0 + 3 * L] = cmulf(make_float2(t1.x - t3.y, t1.y + t3.x), tw[3 * j * m]);
        }
        __syncthreads();
    }

    // Hilbert multiplier h[k] applied at base-4 digit-reversed slot.
    for (int p = tid; p < TT; p += 512) {
        const int r = (int)(__brev((unsigned)p) >> 20);         // 12-bit reverse
        const int k = ((r & 0x555) << 1) | ((r >> 1) & 0x555);  // swap bit pairs
        float h;
        if (k == 0 || k == TT / 2) h = 1.0f;
        else if (k < TT / 2)       h = 2.0f;
        else                       h = 0.0f;
        s[p].x *= h;
        s[p].y *= h;
    }
    __syncthreads();

    // Inverse radix-4 DIT: digit-reversed in, natural out (conj twiddles, no 1/N).
#pragma unroll
    for (int ls = 0; ls <= 10; ls += 2) {
        const int L = 1 << ls;
        const int m = 1024 >> ls;
        for (int i = tid; i < 1024; i += 512) {
            const int j = i & (L - 1);
            const int i0 = ((i >> ls) << (ls + 2)) + j;
            float2 w1 = tw[j * m], w2 = tw[2 * j * m], w3 = tw[3 * j * m];
            float2 A = s[i0];
            float2 Bv = cmulf(s[i0 + L],     make_float2(w1.x, -w1.y));
            float2 Cv = cmulf(s[i0 + 2 * L], make_float2(w2.x, -w2.y));
            float2 Dv = cmulf(s[i0 + 3 * L], make_float2(w3.x, -w3.y));
            float2 t0 = f2add(A, Cv), t1 = f2sub(A, Cv);
            float2 t2 = f2add(Bv, Dv), t3 = f2sub(Bv, Dv);
            s[i0] = f2add(t0, t2);
            s[i0 + L] = make_float2(t1.x - t3.y, t1.y + t3.x);
            s[i0 + 2 * L] = f2sub(t0, t2);
            s[i0 + 3 * L] = make_float2(t1.x + t3.y, t1.y - t3.x);
        }
        __syncthreads();
    }

    float* ph = g_phase + (size_t)row * TT;
    for (int t = tid; t < TT; t += 512)
        ph[t] = atan2f(s[t].y, s[t].x);
}

// ---------------- kernel 2: fused features + HMMA GEMM + argmin ----------
__device__ __forceinline__ void prefetch_chunk(uint32_t sdst, int ch, int tid) {
    const char* src = (const char*)g_B + (size_t)ch * CROWS * KTOT * 2;
#pragma unroll
    for (int it = 0; it < 6; ++it) {
        const int i = tid + it * 256;       // 1536 uint4 total
        const int r = i / 24, kq = i - r * 24;
        CP_ASYNC16(sdst + (uint32_t)r * KP_B + (uint32_t)kq * 16u,
                   src + (size_t)r * 384 + (size_t)kq * 16);
    }
    CP_COMMIT();
}

__global__ void __launch_bounds__(256, 2)
quant_kernel(const float* __restrict__ imu,
             const float* __restrict__ Wm,
             const float* __restrict__ bm,
             const float* __restrict__ Wp,
             const float* __restrict__ bp,
             const float* __restrict__ cb,
             float* __restrict__ out) {
    extern __shared__ char smem[];
    const uint32_t sbase = smem_to_u32(smem);
    const int tid = threadIdx.x;
    const int wid = tid >> 5;
    const int lane = tid & 31;
    const int pbase = blockIdx.x * MBLK;

    float* scn = (float*)(smem + SM_CN);
    float* rbv = (float*)(smem + SM_RBV);
    int* rbi = (int*)(smem + SM_RBI);
    int* sidx = (int*)(smem + SM_IDX);

    // start B pipeline before the heavy feature phase
    prefetch_chunk(sbase + SM_B0, 0, tid);
    prefetch_chunk(sbase + SM_B1, 1, tid);

    for (int i = tid; i < NC; i += 256) scn[i] = g_cn[i];

    // ---- features for 128 positions -> SMEM A (bf16 split)
    if (tid < MBLK) {
        const int p = pbase + tid;
        const int b = p >> 12;
        const int t = p & (TT - 1);

        const float* xb = imu + (size_t)b * CC * TT + t;
        float xc[9];
#pragma unroll
        for (int c = 0; c < 9; ++c) xc[c] = xb[c * TT];

        const float* phb = g_phase + (size_t)b * CC * TT + t;
        float pm = 0.0f;
#pragma unroll
        for (int c = 0; c < 9; ++c) pm += phb[c * TT];
        pm *= (1.0f / 9.0f);
        float sp, cp;
        sincosf(pm, &sp, &cp);
        out[OFF_PH + p] = pm;

        float f[64];
#pragma unroll
        for (int i = 0; i < 32; ++i) {
            float a = bm[i];
#pragma unroll
            for (int c = 0; c < 9; ++c) a += Wm[i * 9 + c] * xc[c];
            f[i] = a;
        }
        float comb[9];
#pragma unroll
        for (int c = 0; c < 7; ++c) comb[c] = xc[c];
        comb[7] = cp;
        comb[8] = sp;
#pragma unroll
        for (int i = 0; i < 32; ++i) {
            float a = bp[i];
#pragma unroll
            for (int c = 0; c < 9; ++c) a += Wp[i * 9 + c] * comb[c];
            f[32 + i] = a;
        }

        uint32_t* row32 = (uint32_t*)(smem + SM_A + (uint32_t)tid * KP_B);
#pragma unroll
        for (int q = 0; q < 32; ++q) {
            uint32_t hp, lp;
            split_pack(f[2 * q], f[2 * q + 1], hp, lp);
            row32[q] = hp;            // seg0: f_hi
            row32[32 + q] = lp;       // seg1: f_lo
            row32[64 + q] = hp;       // seg2: f_hi
        }
    }
    __syncthreads();   // A + cn visible

    // ---- GEMM + argmin. Warp tile m64 x n16: wrow = wid&1, wcol = wid>>1.
    const int wrow = wid & 1;
    const int wcol = wid >> 1;
    const int m0 = wrow * 64;

    float best[8];
    int bidx[8];
#pragma unroll
    for (int i = 0; i < 8; ++i) { best[i] = CUDART_INF_F; bidx[i] = 0; }

    const int mgrp = lane >> 3;     // 0..3
    const int mrow = lane & 7;
    const uint32_t a_base = sbase + SM_A
        + (uint32_t)(m0 + mrow + 8 * (mgrp & 1)) * KP_B
        + (uint32_t)(8 * (mgrp >> 1)) * 2u;
    const uint32_t b_off = (uint32_t)(wcol * 16) * KP_B
        + (uint32_t)(8 * (mgrp >> 1) + mrow) * KP_B
        + (uint32_t)(8 * (mgrp & 1)) * 2u;

#pragma unroll 1
    for (int ch = 0; ch < 8; ++ch) {
        if (ch < 7) { CP_WAIT(1); } else { CP_WAIT(0); }
        __syncthreads();            // chunk buffer complete for all warps

        const uint32_t sB = sbase + ((ch & 1) ? SM_B1 : SM_B0);

        float acc[4][2][4];
#pragma unroll
        for (int mt = 0; mt < 4; ++mt)
#pragma unroll
            for (int j = 0; j < 2; ++j)
#pragma unroll
                for (int q = 0; q < 4; ++q) acc[mt][j][q] = 0.0f;

#pragma unroll
        for (int ks = 0; ks < 12; ++ks) {
            const uint32_t koff = (uint32_t)ks * 32u;
            uint32_t bq0, bq1, bq2, bq3;
            LDSM_X4(bq0, bq1, bq2, bq3, sB + b_off + koff);
#pragma unroll
            for (int mt = 0; mt < 4; ++mt) {
                uint32_t a[4];
                LDSM_X4(a[0], a[1], a[2], a[3],
                        a_base + (uint32_t)mt * (16u * KP_B) + koff);
                MMA16816(acc[mt][0], a, bq0, bq1);
                MMA16816(acc[mt][1], a, bq2, bq3);
            }
        }

        // running argmin (codes strictly increasing -> first-min kept)
#pragma unroll
        for (int mt = 0; mt < 4; ++mt)
#pragma unroll
            for (int j = 0; j < 2; ++j) {
                const int c0 = ch * CROWS + wcol * 16 + j * 8 + (lane & 3) * 2;
                const float n0v = scn[c0], n1v = scn[c0 + 1];
                const float d0 = fmaf(-2.0f, acc[mt][j][0], n0v);
                const float d1 = fmaf(-2.0f, acc[mt][j][1], n1v);
                const float d2 = fmaf(-2.0f, acc[mt][j][2], n0v);
                const float d3 = fmaf(-2.0f, acc[mt][j][3], n1v);
                const int s0 = 2 * mt, s1 = 2 * mt + 1;
                if (d0 < best[s0]) { best[s0] = d0; bidx[s0] = c0; }
                if (d1 < best[s0]) { best[s0] = d1; bidx[s0] = c0 + 1; }
                if (d2 < best[s1]) { best[s1] = d2; bidx[s1] = c0; }
                if (d3 < best[s1]) { best[s1] = d3; bidx[s1] = c0 + 1; }
            }

        __syncthreads();            // all warps done reading this buffer
        if (ch < 6) prefetch_chunk(sbase + ((ch & 1) ? SM_B1 : SM_B0),
                                   ch + 2, tid);
    }

    // reduce across the 4 lanes sharing each row (quad)
#pragma unroll
    for (int off = 1; off <= 2; off <<= 1) {
#pragma unroll
        for (int s = 0; s < 8; ++s) {
            float ob = __shfl_xor_sync(0xffffffffu, best[s], off);
            int oi = __shfl_xor_sync(0xffffffffu, bidx[s], off);
            if (ob < best[s] || (ob == best[s] && oi < bidx[s])) {
                best[s] = ob; bidx[s] = oi;
            }
        }
    }
    if ((lane & 3) == 0) {
        const int r = lane >> 2;
#pragma unroll
        for (int mt = 0; mt < 4; ++mt)
#pragma unroll
            for (int h = 0; h < 2; ++h) {
                const int row = m0 + mt * 16 + 8 * h + r;
                rbv[row * 4 + wcol] = best[2 * mt + h];
                rbi[row * 4 + wcol] = bidx[2 * mt + h];
            }
    }
    __syncthreads();

    // cross-warpcol reduce: one thread per row
    if (tid < MBLK) {
        float bv = rbv[tid * 4];
        int bi = rbi[tid * 4];
#pragma unroll
        for (int w = 1; w < 4; ++w) {
            const float ov = rbv[tid * 4 + w];
            const int oi = rbi[tid * 4 + w];
            if (ov < bv || (ov == bv && oi < bi)) { bv = ov; bi = oi; }
        }
        sidx[tid] = bi;
        out[OFF_IDX + pbase + tid] = (float)bi;
    }
    __syncthreads();

    // quantized rows from fp32 codebook (L2-hot)
    const float4* cb4 = (const float4*)cb;
    for (int q = tid; q < MBLK * (CD / 4); q += 256) {
        const int pos = q >> 4;
        const int w = q & 15;
        ((float4*)(out + (size_t)(pbase + pos) * CD))[w] =
            cb4[(size_t)sidx[pos] * (CD / 4) + w];
    }
}

// ---------------- launch ----------------
extern "C" void kernel_launch(void* const* d_in, const int* in_sizes, int n_in,
                              void* d_out, int out_size) {
    const float* imu = (const float*)d_in[0];
    const float* Wm  = (const float*)d_in[1];
    const float* bm  = (const float*)d_in[2];
    const float* Wp  = (const float*)d_in[3];
    const float* bp  = (const float*)d_in[4];
    const float* cb  = (const float*)d_in[5];
    float* out = (float*)d_out;

    const int fft_smem = 2 * TT * (int)sizeof(float2);  // 64 KB
    cudaFuncSetAttribute(fft_conv_kernel,
                         cudaFuncAttributeMaxDynamicSharedMemorySize, fft_smem);
    fft_conv_kernel<<<BB * CC + NC / 16, 512, fft_smem>>>(imu, cb);

    cudaFuncSetAttribute(quant_kernel,
                         cudaFuncAttributeMaxDynamicSharedMemorySize, SMEMSZ);
    quant_kernel<<<(BB * TT) / MBLK, 256, SMEMSZ>>>(imu, Wm, bm, Wp, bp, cb, out);
}